// round 5
// baseline (speedup 1.0000x reference)
#include <cuda_runtime.h>
#include <cuda_bf16.h>

#define B_ 32
#define N_ 256
#define META_CAP (1 << 20)

// Scratch (allocation-free rule: __device__ global)
__device__ int2 g_meta[META_CAP];  // .x = packed sel (-1 = inactive), .y = w1 bits

// ---------------------------------------------------------------------------
// Meta: grid (ceil(T/256), B), 256 threads. Each block:
//  - detects int32 vs int64 (durations < 16, so int64 => all odd words 0;
//    words [1,512) are in-bounds under both interpretations)
//  - rebuilds the inclusive cumsum of its batch row in smem
//  - binary-searches, emits per-frame descriptor + coalesced mask
// sel: bits [0,8)=idx, [8,10)=A source (0=s,1=m,2=e), [10,12)=B source (3=copy)
// ---------------------------------------------------------------------------
__global__ __launch_bounds__(256) void meta_kernel(
    const void* __restrict__ dur_raw,
    const void* __restrict__ rc_raw,
    float* __restrict__ mask_out,
    int T, int write_mask)
{
    __shared__ int cum_s[N_];
    __shared__ int s_is64;
    const int b   = blockIdx.y;
    const int tid = threadIdx.x;

    if (tid < 32) {
        const int* d32 = (const int*)dur_raw;
        int acc = 0;
#pragma unroll
        for (int i = tid; i < 256; i += 32) acc |= d32[2 * i + 1];
        acc = __reduce_or_sync(0xffffffff, acc);
        if (tid == 0) s_is64 = (acc == 0) ? 1 : 0;
    }
    __syncthreads();
    const int is64 = s_is64;

    int v = is64 ? (int)((const long long*)dur_raw)[b * N_ + tid]
                 : ((const int*)dur_raw)[b * N_ + tid];
    cum_s[tid] = v;
    __syncthreads();
#pragma unroll
    for (int off = 1; off < N_; off <<= 1) {
        int add = (tid >= off) ? cum_s[tid - off] : 0;
        __syncthreads();
        cum_s[tid] += add;
        __syncthreads();
    }

    const int t = blockIdx.x * 256 + tid;
    if (t >= T) return;

    const int total = cum_s[N_ - 1];
    const bool active = (t < total);
    if (write_mask) mask_out[(long long)b * T + t] = active ? 1.0f : 0.0f;

    int2 mv;
    if (!active) {
        mv.x = -1; mv.y = 0;
    } else {
        int lo = 0, hi = N_;
        while (lo < hi) {
            int m = (lo + hi) >> 1;
            if (cum_s[m] <= t) lo = m + 1; else hi = m;
        }
        int idx = lo < (N_ - 1) ? lo : (N_ - 1);

        const int d = cum_s[idx] - (idx ? cum_s[idx - 1] : 0);
        int cls = is64 ? (int)((const long long*)rc_raw)[b * N_ + idx]
                       : ((const int*)rc_raw)[b * N_ + idx];
        const int p = t - (cum_s[idx] - d);

        const bool is_first   = (p == 0) && (d > 1);
        const bool is_last    = (p == d - 1) && (d > 1);
        const int  half       = d >> 1;
        const bool use_linear = (cls == 1) && (d >= 4);

        int aS, bS;
        float w1 = 0.0f;
        if (use_linear) {
            if (p < half) {
                int den = half - 1; if (den < 1) den = 1;
                aS = 0; bS = 1; w1 = (float)p / (float)den;
            } else {
                int den = d - half - 1; if (den < 1) den = 1;
                aS = 1; bS = 2; w1 = (float)(p - half) / (float)den;
            }
        } else {
            aS = is_first ? 0 : (is_last ? 2 : 1);
            bS = 3;
        }
        mv.x = idx | (aS << 8) | (bS << 10);
        mv.y = __float_as_int(w1);
    }
    g_meta[(long long)b * T + t] = mv;
}

// ---------------------------------------------------------------------------
// Frame: 256-thread block = 2 groups x 128 threads; each group streams 4
// consecutive frames of one batch. Phase 1 issues all row loads (MLP up to
// 8 x 16B per thread); phase 2 recomputes control from smem meta (cheap LDS)
// and stores. Register state across phases = av/bv only -> <=51 regs with
// __launch_bounds__(256,5) for 5 blocks/SM.
// ---------------------------------------------------------------------------
__global__ __launch_bounds__(256, 5) void frame_kernel(
    const float4* __restrict__ start,
    const float4* __restrict__ mid,
    const float4* __restrict__ end,
    float4* __restrict__ out,
    int T, int F4)
{
    __shared__ int2 meta_s[8];
    const int b     = blockIdx.y;
    const int grp   = threadIdx.x >> 7;     // 0 or 1
    const int f0    = threadIdx.x & 127;
    const int tbase = blockIdx.x * 8 + grp * 4;

    if (threadIdx.x < 8) {
        int tt = blockIdx.x * 8 + threadIdx.x;
        meta_s[threadIdx.x] = (tt < T) ? g_meta[(long long)b * T + tt]
                                       : make_int2(-1, 0);
    }
    __syncthreads();

    float4 av[4], bv[4];

    // Phase 1: issue all independent loads.
#pragma unroll
    for (int k = 0; k < 4; ++k) {
        const int sel = meta_s[grp * 4 + k].x;
        if (sel >= 0) {
            const int idx = sel & 255;
            const int aS  = (sel >> 8) & 3;
            const int bS  = (sel >> 10) & 3;
            const long long rb = ((long long)b * N_ + idx) * (long long)F4 + f0;
            const float4* __restrict__ A =
                (aS == 0) ? start : ((aS == 1) ? mid : end);
            av[k] = __ldg(A + rb);
            if (bS != 3) {
                const float4* __restrict__ Bp = (bS == 1) ? mid : end;
                bv[k] = __ldg(Bp + rb);
            }
        }
    }

    // Phase 2: compute + store. Control re-derived from smem meta.
    const long long obase = ((long long)b * T + tbase) * (long long)F4 + f0;
#pragma unroll
    for (int k = 0; k < 4; ++k) {
        if (tbase + k >= T) continue;
        const int2 mv = meta_s[grp * 4 + k];
        const int sel = mv.x;
        float4 r;
        if (sel < 0) {
            r = make_float4(0.f, 0.f, 0.f, 0.f);
        } else if (((sel >> 10) & 3) == 3) {
            r = av[k];
        } else {
            const float w1 = __int_as_float(mv.y);
            const float w0 = 1.0f - w1;
            r.x = fmaf(av[k].x, w0, bv[k].x * w1);
            r.y = fmaf(av[k].y, w0, bv[k].y * w1);
            r.z = fmaf(av[k].z, w0, bv[k].z * w1);
            r.w = fmaf(av[k].w, w0, bv[k].w * w1);
        }
        __stcs(out + obase + (long long)k * F4, r);
    }
}

// ---------------------------------------------------------------------------
// Launch
// ---------------------------------------------------------------------------
extern "C" void kernel_launch(void* const* d_in, const int* in_sizes, int n_in,
                              void* d_out, int out_size) {
    const float* start = (const float*)d_in[0];
    const float* mid   = (const float*)d_in[1];
    const float* end   = (const float*)d_in[2];
    const void*  dur   = d_in[3];
    const void*  rc    = d_in[4];
    (void)n_in;

    const int BN = in_sizes[3];                 // B*N
    const int F  = in_sizes[0] / BN;            // 512
    const int F4 = F / 4;

    long long os = (long long)out_size;
    int T, write_mask;
    if (os % ((long long)B_ * (F + 1)) == 0) {
        T = (int)(os / ((long long)B_ * (F + 1)));
        write_mask = 1;
    } else {
        T = (int)(os / ((long long)B_ * F));
        write_mask = 0;
    }

    float* out_f  = (float*)d_out;
    float* mask_f = out_f + (long long)B_ * T * F;

    dim3 mgrid((T + 255) / 256, B_);
    meta_kernel<<<mgrid, 256>>>(dur, rc, mask_f, T, write_mask);
    dim3 fgrid((T + 7) / 8, B_);
    frame_kernel<<<fgrid, 256>>>(
        (const float4*)start, (const float4*)mid, (const float4*)end,
        (float4*)out_f, T, F4);
}

// round 6
// speedup vs baseline: 1.0198x; 1.0198x over previous
#include <cuda_runtime.h>
#include <cuda_bf16.h>

#define B_ 32
#define N_ 256
#define META_CAP (1 << 20)

// Scratch (allocation-free rule: __device__ global)
__device__ int2 g_meta[META_CAP];  // .x = packed sel (-1 = inactive), .y = w1 bits

// ---------------------------------------------------------------------------
// Meta: grid (ceil(T/256), B), 256 threads. Each block:
//  - detects int32 vs int64 (durations < 16, so int64 => all odd words 0;
//    words [1,512) are in-bounds under both interpretations)
//  - rebuilds the inclusive cumsum of its batch row in smem
//  - binary-searches, emits per-frame descriptor + coalesced mask
// sel: bits [0,8)=idx, [8,10)=A source (0=s,1=m,2=e), [10,12)=B source (3=copy)
// ---------------------------------------------------------------------------
__global__ __launch_bounds__(256) void meta_kernel(
    const void* __restrict__ dur_raw,
    const void* __restrict__ rc_raw,
    float* __restrict__ mask_out,
    int T, int write_mask)
{
    __shared__ int cum_s[N_];
    __shared__ int s_is64;
    const int b   = blockIdx.y;
    const int tid = threadIdx.x;

    if (tid < 32) {
        const int* d32 = (const int*)dur_raw;
        int acc = 0;
#pragma unroll
        for (int i = tid; i < 256; i += 32) acc |= d32[2 * i + 1];
        acc = __reduce_or_sync(0xffffffff, acc);
        if (tid == 0) s_is64 = (acc == 0) ? 1 : 0;
    }
    __syncthreads();
    const int is64 = s_is64;

    int v = is64 ? (int)((const long long*)dur_raw)[b * N_ + tid]
                 : ((const int*)dur_raw)[b * N_ + tid];
    cum_s[tid] = v;
    __syncthreads();
#pragma unroll
    for (int off = 1; off < N_; off <<= 1) {
        int add = (tid >= off) ? cum_s[tid - off] : 0;
        __syncthreads();
        cum_s[tid] += add;
        __syncthreads();
    }

    const int t = blockIdx.x * 256 + tid;
    if (t >= T) return;

    const int total = cum_s[N_ - 1];
    const bool active = (t < total);
    if (write_mask) mask_out[b * T + t] = active ? 1.0f : 0.0f;

    int2 mv;
    if (!active) {
        mv.x = -1; mv.y = 0;
    } else {
        int lo = 0, hi = N_;
        while (lo < hi) {
            int m = (lo + hi) >> 1;
            if (cum_s[m] <= t) lo = m + 1; else hi = m;
        }
        int idx = lo < (N_ - 1) ? lo : (N_ - 1);

        const int d = cum_s[idx] - (idx ? cum_s[idx - 1] : 0);
        int cls = is64 ? (int)((const long long*)rc_raw)[b * N_ + idx]
                       : ((const int*)rc_raw)[b * N_ + idx];
        const int p = t - (cum_s[idx] - d);

        const bool is_first   = (p == 0) && (d > 1);
        const bool is_last    = (p == d - 1) && (d > 1);
        const int  half       = d >> 1;
        const bool use_linear = (cls == 1) && (d >= 4);

        int aS, bS;
        float w1 = 0.0f;
        if (use_linear) {
            if (p < half) {
                int den = half - 1; if (den < 1) den = 1;
                aS = 0; bS = 1; w1 = (float)p / (float)den;
            } else {
                int den = d - half - 1; if (den < 1) den = 1;
                aS = 1; bS = 2; w1 = (float)(p - half) / (float)den;
            }
        } else {
            aS = is_first ? 0 : (is_last ? 2 : 1);
            bS = 3;
        }
        mv.x = idx | (aS << 8) | (bS << 10);
        mv.y = __float_as_int(w1);
    }
    g_meta[b * T + t] = mv;
}

// ---------------------------------------------------------------------------
// Frame: 256-thread block = 2 groups x 128 threads; each group streams 4
// consecutive frames of one batch. No smem, no syncthreads: every thread
// __ldg's its group's 4 meta entries (same address across the group ->
// L1 broadcast). Phase 1 issues all row loads (MLP up to 8 x 16B/thread);
// phase 2 computes + streaming-stores. All addressing is int32.
// ---------------------------------------------------------------------------
__global__ __launch_bounds__(256, 5) void frame_kernel(
    const float4* __restrict__ start,
    const float4* __restrict__ mid,
    const float4* __restrict__ end,
    float4* __restrict__ out,
    int T, int F4)
{
    const int b     = blockIdx.y;
    const int grp   = threadIdx.x >> 7;     // 0 or 1
    const int f0    = threadIdx.x & 127;
    const int tbase = blockIdx.x * 8 + grp * 4;

    // Per-group meta (broadcast loads; g_meta is sized so reads past T stay
    // in-bounds, and stores below are guarded by t < T).
    const int2* __restrict__ mp = g_meta + b * T + tbase;
    int2 mv[4];
#pragma unroll
    for (int k = 0; k < 4; ++k) mv[k] = __ldg(mp + k);

    const int rowf = b * N_ * F4 + f0;      // base into feature tensors

    float4 av[4], bv[4];

    // Phase 1: issue all independent loads.
#pragma unroll
    for (int k = 0; k < 4; ++k) {
        const int sel = mv[k].x;
        if (sel >= 0) {
            const int idx = sel & 255;
            const int aS  = (sel >> 8) & 3;
            const int bS  = (sel >> 10) & 3;
            const int rb  = rowf + idx * F4;
            const float4* __restrict__ A =
                (aS == 0) ? start : ((aS == 1) ? mid : end);
            av[k] = __ldg(A + rb);
            if (bS != 3) {
                const float4* __restrict__ Bp = (bS == 1) ? mid : end;
                bv[k] = __ldg(Bp + rb);
            }
        }
    }

    // Phase 2: compute + store.
    const int obase = (b * T + tbase) * F4 + f0;
#pragma unroll
    for (int k = 0; k < 4; ++k) {
        if (tbase + k >= T) continue;
        const int sel = mv[k].x;
        float4 r;
        if (sel < 0) {
            r = make_float4(0.f, 0.f, 0.f, 0.f);
        } else if (((sel >> 10) & 3) == 3) {
            r = av[k];
        } else {
            const float w1 = __int_as_float(mv[k].y);
            const float w0 = 1.0f - w1;
            r.x = fmaf(av[k].x, w0, bv[k].x * w1);
            r.y = fmaf(av[k].y, w0, bv[k].y * w1);
            r.z = fmaf(av[k].z, w0, bv[k].z * w1);
            r.w = fmaf(av[k].w, w0, bv[k].w * w1);
        }
        __stcs(out + obase + k * F4, r);
    }
}

// ---------------------------------------------------------------------------
// Launch
// ---------------------------------------------------------------------------
extern "C" void kernel_launch(void* const* d_in, const int* in_sizes, int n_in,
                              void* d_out, int out_size) {
    const float* start = (const float*)d_in[0];
    const float* mid   = (const float*)d_in[1];
    const float* end   = (const float*)d_in[2];
    const void*  dur   = d_in[3];
    const void*  rc    = d_in[4];
    (void)n_in;

    const int BN = in_sizes[3];                 // B*N
    const int F  = in_sizes[0] / BN;            // 512
    const int F4 = F / 4;

    long long os = (long long)out_size;
    int T, write_mask;
    if (os % ((long long)B_ * (F + 1)) == 0) {
        T = (int)(os / ((long long)B_ * (F + 1)));
        write_mask = 1;
    } else {
        T = (int)(os / ((long long)B_ * F));
        write_mask = 0;
    }

    float* out_f  = (float*)d_out;
    float* mask_f = out_f + B_ * T * F;

    dim3 mgrid((T + 255) / 256, B_);
    meta_kernel<<<mgrid, 256>>>(dur, rc, mask_f, T, write_mask);
    dim3 fgrid((T + 7) / 8, B_);
    frame_kernel<<<fgrid, 256>>>(
        (const float4*)start, (const float4*)mid, (const float4*)end,
        (float4*)out_f, T, F4);
}

// round 7
// speedup vs baseline: 1.1324x; 1.1105x over previous
#include <cuda_runtime.h>
#include <cuda_bf16.h>

#define B_ 32
#define N_ 256

// Scratch (allocation-free rule: __device__ globals)
__device__ int g_cum[B_ * N_];
__device__ int g_total[B_];
__device__ int g_is64;

// ---------------------------------------------------------------------------
// Setup: per-batch inclusive scan of durations + int32/int64 detection.
// (durations < 16: if int64, all odd 32-bit words are 0; words [1,512) are
// in-bounds under both interpretations.)
// ---------------------------------------------------------------------------
__global__ __launch_bounds__(256) void setup_kernel(const void* __restrict__ dur_raw) {
    __shared__ int s[N_];
    __shared__ int s_is64;
    const int b = blockIdx.x;
    const int i = threadIdx.x;

    if (i < 32) {
        const int* d32 = (const int*)dur_raw;
        int acc = 0;
#pragma unroll
        for (int k = i; k < 256; k += 32) acc |= d32[2 * k + 1];
        acc = __reduce_or_sync(0xffffffff, acc);
        if (i == 0) {
            s_is64 = (acc == 0) ? 1 : 0;
            if (b == 0) g_is64 = s_is64;
        }
    }
    __syncthreads();
    const int is64 = s_is64;

    int v = is64 ? (int)((const long long*)dur_raw)[b * N_ + i]
                 : ((const int*)dur_raw)[b * N_ + i];
    s[i] = v;
    __syncthreads();
#pragma unroll
    for (int off = 1; off < N_; off <<= 1) {
        int add = (i >= off) ? s[i - off] : 0;
        __syncthreads();
        s[i] += add;
        __syncthreads();
    }
    g_cum[b * N_ + i] = s[i];
    if (i == N_ - 1) g_total[b] = s[i];
}

// ---------------------------------------------------------------------------
// Main fused kernel, 128 threads/block, grid (N_ + ceil(T/4), B_):
//  blockIdx.x <  N_           -> segment block: load source rows ONCE into
//                                registers, stream-store all d frames.
//  blockIdx.x >= N_           -> tail block: 4 frames; write mask; zero-fill
//                                frames >= total (contiguous tail).
// All control is block-uniform.
// ---------------------------------------------------------------------------
__global__ __launch_bounds__(128) void main_kernel(
    const float4* __restrict__ start,
    const float4* __restrict__ mid,
    const float4* __restrict__ end,
    const void* __restrict__ rc_raw,
    float4* __restrict__ out,
    float* __restrict__ mask_out,
    int T, int F4, int write_mask)
{
    const int b  = blockIdx.y;
    const int f0 = threadIdx.x;

    if (blockIdx.x >= N_) {
        // ---- tail / mask block: frames [tb, tb+4) ----
        const int tb = (blockIdx.x - N_) * 4;
        int total = g_total[b]; if (total > T) total = T;
        if (write_mask && f0 < 4 && tb + f0 < T) {
            mask_out[b * T + tb + f0] = (tb + f0 < total) ? 1.0f : 0.0f;
        }
        if (tb + 4 <= total) return;          // fully active: nothing to zero
        const float4 z = make_float4(0.f, 0.f, 0.f, 0.f);
        const int ob = (b * T + tb) * F4 + f0;
#pragma unroll
        for (int k = 0; k < 4; ++k) {
            const int t = tb + k;
            if (t >= total && t < T) __stcs(out + ob + k * F4, z);
        }
        return;
    }

    // ---- segment block ----
    const int idx = blockIdx.x;
    const int c1 = g_cum[b * N_ + idx];
    const int c0 = idx ? g_cum[b * N_ + idx - 1] : 0;
    const int d  = c1 - c0;
    if (d <= 0) return;
    const int off = c0;
    if (off >= T) return;

    const int cls = g_is64 ? (int)((const long long*)rc_raw)[b * N_ + idx]
                           : ((const int*)rc_raw)[b * N_ + idx];
    const bool lin = (cls == 1) && (d >= 4);

    const int rb = (b * N_ + idx) * F4 + f0;
    // Load only the rows this segment needs, once.
    const bool need_s = lin || (d > 1);
    const bool need_e = lin || (d > 1);
    const bool need_m = lin || (d != 2);
    float4 s, m, e;
    if (need_s) s = __ldg(start + rb);
    if (need_m) m = __ldg(mid + rb);
    if (need_e) e = __ldg(end + rb);

    int pe = d; if (off + pe > T) pe = T - off;
    const int half = d >> 1;
    int den1 = half - 1;     if (den1 < 1) den1 = 1;
    int den2 = d - half - 1; if (den2 < 1) den2 = 1;
    const float inv1 = 1.0f / (float)den1;
    const float inv2 = 1.0f / (float)den2;

    float4* __restrict__ ob = out + (b * T + off) * F4 + f0;

    if (lin) {
#pragma unroll 4
        for (int p = 0; p < pe; ++p) {
            const bool first_half = (p < half);
            const float w1 = first_half ? (float)p * inv1
                                        : (float)(p - half) * inv2;
            const float w0 = 1.0f - w1;
            const float4 A = first_half ? s : m;
            const float4 Bv = first_half ? m : e;
            float4 r;
            r.x = fmaf(A.x, w0, Bv.x * w1);
            r.y = fmaf(A.y, w0, Bv.y * w1);
            r.z = fmaf(A.z, w0, Bv.z * w1);
            r.w = fmaf(A.w, w0, Bv.w * w1);
            __stcs(ob + p * F4, r);
        }
    } else {
#pragma unroll 4
        for (int p = 0; p < pe; ++p) {
            float4 r = m;
            if (d > 1) {
                if (p == 0)          r = s;
                else if (p == d - 1) r = e;
            }
            __stcs(ob + p * F4, r);
        }
    }
}

// ---------------------------------------------------------------------------
// Launch
// ---------------------------------------------------------------------------
extern "C" void kernel_launch(void* const* d_in, const int* in_sizes, int n_in,
                              void* d_out, int out_size) {
    const float* start = (const float*)d_in[0];
    const float* mid   = (const float*)d_in[1];
    const float* end   = (const float*)d_in[2];
    const void*  dur   = d_in[3];
    const void*  rc    = d_in[4];
    (void)n_in;

    const int BN = in_sizes[3];                 // B*N
    const int F  = in_sizes[0] / BN;            // 512
    const int F4 = F / 4;

    long long os = (long long)out_size;
    int T, write_mask;
    if (os % ((long long)B_ * (F + 1)) == 0) {
        T = (int)(os / ((long long)B_ * (F + 1)));
        write_mask = 1;
    } else {
        T = (int)(os / ((long long)B_ * F));
        write_mask = 0;
    }

    float* out_f  = (float*)d_out;
    float* mask_f = out_f + B_ * T * F;

    setup_kernel<<<B_, 256>>>(dur);
    const int tail_blocks = (T + 3) / 4;
    dim3 grid(N_ + tail_blocks, B_);
    main_kernel<<<grid, 128>>>(
        (const float4*)start, (const float4*)mid, (const float4*)end,
        rc, (float4*)out_f, mask_f, T, F4, write_mask);
}

// round 8
// speedup vs baseline: 1.1767x; 1.0391x over previous
#include <cuda_runtime.h>
#include <cuda_bf16.h>

#define B_ 32
#define N_ 256
#define TAIL_FR 8

// ---------------------------------------------------------------------------
// Single fused kernel. Grid (N_ + ceil(T/TAIL_FR), B_), 128 threads.
//   blockIdx.x <  N_  -> segment block (b, idx): derive c0/c1/d by block
//                        reduction over the durations row, then load the <=3
//                        source rows once and stream-store all d frames.
//   blockIdx.x >= N_  -> tail block: 8 frames; mask write + zero-fill of the
//                        contiguous inactive tail [total, T).
// int32/int64 detection: durations < 16, so if int64 every odd 32-bit word of
// the first 512 words is 0 (region in-bounds under both layouts).
// All reductions/barriers complete before any divergent exit.
// ---------------------------------------------------------------------------
__global__ __launch_bounds__(128) void main_kernel(
    const float4* __restrict__ start,
    const float4* __restrict__ mid,
    const float4* __restrict__ end,
    const void* __restrict__ dur_raw,
    const void* __restrict__ rc_raw,
    float4* __restrict__ out,
    float* __restrict__ mask_out,
    int T, int F4, int write_mask)
{
    const int b   = blockIdx.y;
    const int tid = threadIdx.x;
    const bool is_seg = (blockIdx.x < N_);
    const int idx = is_seg ? blockIdx.x : -1;

    __shared__ int shO[4];
    __shared__ int shC[4], shD[4], shT[4];

    // ---- detect int32 vs int64 (first 512 words, broadcast/L1-hot) ----
    const int4* d4 = (const int4*)dur_raw;
    int4 det = __ldg(d4 + tid);
    int odd = det.y | det.w;
    odd = __reduce_or_sync(0xffffffffu, odd);
    if ((tid & 31) == 0) shO[tid >> 5] = odd;
    __syncthreads();
    const int is64 = ((shO[0] | shO[1] | shO[2] | shO[3]) == 0) ? 1 : 0;
    __syncthreads();   // shO reuse safety (none, but keeps ordering simple)

    // ---- load this batch's durations, predicated accumulate ----
    int accC = 0, accD = 0, accT = 0;
    if (is64) {
        // words b*512 + 4*tid -> int4 index b*128 + tid; elements 2tid, 2tid+1
        int4 w = __ldg(d4 + b * 128 + tid);
        const int e0 = 2 * tid, e1 = 2 * tid + 1;
        accT = w.x + w.z;
        if (e0 <= idx) accC += w.x;
        if (e1 <= idx) accC += w.z;
        if (e0 == idx) accD += w.x;
        if (e1 == idx) accD += w.z;
    } else if (tid < 64) {
        // words b*256 + 4*tid -> int4 index b*64 + tid; elements 4tid..4tid+3
        int4 w = __ldg(d4 + b * 64 + tid);
        const int e0 = 4 * tid;
        accT = w.x + w.y + w.z + w.w;
        if (e0 + 0 <= idx) accC += w.x;
        if (e0 + 1 <= idx) accC += w.y;
        if (e0 + 2 <= idx) accC += w.z;
        if (e0 + 3 <= idx) accC += w.w;
        if (e0 + 0 == idx) accD += w.x;
        if (e0 + 1 == idx) accD += w.y;
        if (e0 + 2 == idx) accD += w.z;
        if (e0 + 3 == idx) accD += w.w;
    }
    accC = __reduce_add_sync(0xffffffffu, accC);
    accD = __reduce_add_sync(0xffffffffu, accD);
    accT = __reduce_add_sync(0xffffffffu, accT);
    if ((tid & 31) == 0) {
        shC[tid >> 5] = accC; shD[tid >> 5] = accD; shT[tid >> 5] = accT;
    }
    __syncthreads();
    const int c1    = shC[0] + shC[1] + shC[2] + shC[3];
    const int d     = shD[0] + shD[1] + shD[2] + shD[3];
    const int totalF= shT[0] + shT[1] + shT[2] + shT[3];

    const int f0 = tid;

    if (!is_seg) {
        // ---- tail / mask block: frames [tb, tb+TAIL_FR) ----
        const int tb = (blockIdx.x - N_) * TAIL_FR;
        int total = totalF; if (total > T) total = T;
        if (write_mask && f0 < TAIL_FR && tb + f0 < T) {
            mask_out[b * T + tb + f0] = (tb + f0 < total) ? 1.0f : 0.0f;
        }
        if (tb + TAIL_FR <= total) return;    // fully active: nothing to zero
        const float4 z = make_float4(0.f, 0.f, 0.f, 0.f);
        const int ob = (b * T + tb) * F4 + f0;
#pragma unroll
        for (int k = 0; k < TAIL_FR; ++k) {
            const int t = tb + k;
            if (t >= total && t < T) __stcs(out + ob + k * F4, z);
        }
        return;
    }

    // ---- segment block ----
    if (d <= 0) return;
    const int off = c1 - d;
    if (off >= T) return;

    const int cls = is64 ? (int)((const long long*)rc_raw)[b * N_ + idx]
                         : ((const int*)rc_raw)[b * N_ + idx];
    const bool lin = (cls == 1) && (d >= 4);

    const int rb = (b * N_ + idx) * F4 + f0;
    const bool need_s = lin || (d > 1);
    const bool need_e = lin || (d > 1);
    const bool need_m = lin || (d != 2);
    float4 s, m, e;
    if (need_s) s = __ldg(start + rb);
    if (need_m) m = __ldg(mid + rb);
    if (need_e) e = __ldg(end + rb);

    int pe = d; if (off + pe > T) pe = T - off;
    const int half = d >> 1;
    int den1 = half - 1;     if (den1 < 1) den1 = 1;
    int den2 = d - half - 1; if (den2 < 1) den2 = 1;
    const float inv1 = 1.0f / (float)den1;
    const float inv2 = 1.0f / (float)den2;

    float4* __restrict__ ob = out + (b * T + off) * F4 + f0;

    if (lin) {
#pragma unroll 4
        for (int p = 0; p < pe; ++p) {
            const bool fh = (p < half);
            const float w1 = fh ? (float)p * inv1 : (float)(p - half) * inv2;
            const float w0 = 1.0f - w1;
            const float4 A  = fh ? s : m;
            const float4 Bv = fh ? m : e;
            float4 r;
            r.x = fmaf(A.x, w0, Bv.x * w1);
            r.y = fmaf(A.y, w0, Bv.y * w1);
            r.z = fmaf(A.z, w0, Bv.z * w1);
            r.w = fmaf(A.w, w0, Bv.w * w1);
            __stcs(ob + p * F4, r);
        }
    } else {
#pragma unroll 4
        for (int p = 0; p < pe; ++p) {
            float4 r = m;
            if (d > 1) {
                if (p == 0)          r = s;
                else if (p == d - 1) r = e;
            }
            __stcs(ob + p * F4, r);
        }
    }
}

// ---------------------------------------------------------------------------
// Launch
// ---------------------------------------------------------------------------
extern "C" void kernel_launch(void* const* d_in, const int* in_sizes, int n_in,
                              void* d_out, int out_size) {
    const float* start = (const float*)d_in[0];
    const float* mid   = (const float*)d_in[1];
    const float* end   = (const float*)d_in[2];
    const void*  dur   = d_in[3];
    const void*  rc    = d_in[4];
    (void)n_in;

    const int BN = in_sizes[3];                 // B*N
    const int F  = in_sizes[0] / BN;            // 512
    const int F4 = F / 4;

    long long os = (long long)out_size;
    int T, write_mask;
    if (os % ((long long)B_ * (F + 1)) == 0) {
        T = (int)(os / ((long long)B_ * (F + 1)));
        write_mask = 1;
    } else {
        T = (int)(os / ((long long)B_ * F));
        write_mask = 0;
    }

    float* out_f  = (float*)d_out;
    float* mask_f = out_f + B_ * T * F;

    const int tail_blocks = (T + TAIL_FR - 1) / TAIL_FR;
    dim3 grid(N_ + tail_blocks, B_);
    main_kernel<<<grid, 128>>>(
        (const float4*)start, (const float4*)mid, (const float4*)end,
        dur, rc, (float4*)out_f, mask_f, T, F4, write_mask);
}